// round 6
// baseline (speedup 1.0000x reference)
#include <cuda_runtime.h>
#include <cuda_bf16.h>
#include <math.h>

// HumanPoseModule: fused 6D-rot -> FK -> axis-angle
// d_in[0] = glb_reduced_6d (BT,10,6) f32   rows: joints [1,2,3,6,9,12,13,14,16,17]
// d_in[1] = orientation_6d (BT,6,6)  f32   rows: joints [0,4,5,15,18,19]
// out      = (BT,24,3) f32
//
// 16 lanes per sample, one joint per lane; parent matrices via __shfl_sync(width=16).
// Lanes 0-3 (parent = root) use their local broadcast root as Fp (no shuffle consume).
// Outputs staged per-warp in smem, then written as coalesced float4.

__device__ __forceinline__ void rot6d_to_mat(const float* d6, float* m) {
    float a1x = d6[0], a1y = d6[1], a1z = d6[2];
    float a2x = d6[3], a2y = d6[4], a2z = d6[5];
    float r1 = rsqrtf(a1x * a1x + a1y * a1y + a1z * a1z);
    float b1x = a1x * r1, b1y = a1y * r1, b1z = a1z * r1;
    float d = b1x * a2x + b1y * a2y + b1z * a2z;
    float b2x = a2x - d * b1x, b2y = a2y - d * b1y, b2z = a2z - d * b1z;
    float r2 = rsqrtf(b2x * b2x + b2y * b2y + b2z * b2z);
    b2x *= r2; b2y *= r2; b2z *= r2;
    m[0] = b1x; m[1] = b1y; m[2] = b1z;
    m[3] = b2x; m[4] = b2y; m[5] = b2z;
    m[6] = b1y * b2z - b1z * b2y;
    m[7] = b1z * b2x - b1x * b2z;
    m[8] = b1x * b2y - b1y * b2x;
}

// atan(a) for a in [0,1], minimax poly (abs err ~1e-6 rad)
__device__ __forceinline__ float fast_atan01(float a) {
    float s = a * a;
    float r = -0.0117212f;
    r = fmaf(r, s, 0.05265332f);
    r = fmaf(r, s, -0.11643287f);
    r = fmaf(r, s, 0.19354346f);
    r = fmaf(r, s, -0.33262347f);
    r = fmaf(r, s, 0.99997726f);
    return r * a;
}

// matrix -> quaternion -> axis-angle (reference-faithful pivot selection).
// Quaternion scale folded into one output coefficient (atan2 & sin-ratio are
// invariant under positive scaling of (w,x,y,z)).
__device__ __forceinline__ void mat_to_aa(const float* m, float* __restrict__ aa) {
    float m00 = m[0], m01 = m[1], m02 = m[2];
    float m10 = m[3], m11 = m[4], m12 = m[5];
    float m20 = m[6], m21 = m[7], m22 = m[8];

    float t0 = fmaxf(1.0f + m00 + m11 + m22, 0.0f);
    float t1 = fmaxf(1.0f + m00 - m11 - m22, 0.0f);
    float t2 = fmaxf(1.0f - m00 + m11 - m22, 0.0f);
    float t3 = fmaxf(1.0f - m00 - m11 + m22, 0.0f);

    float best = t0; int idx = 0;
    if (t1 > best) { best = t1; idx = 1; }
    if (t2 > best) { best = t2; idx = 2; }
    if (t3 > best) { best = t3; idx = 3; }

    float w, x, y, z;   // UNscaled quaternion (positive multiple of reference's)
    if (idx == 0)      { w = best;      x = m21 - m12; y = m02 - m20; z = m10 - m01; }
    else if (idx == 1) { w = m21 - m12; x = best;      y = m10 + m01; z = m02 + m20; }
    else if (idx == 2) { w = m02 - m20; x = m10 + m01; y = best;      z = m12 + m21; }
    else               { w = m10 - m01; x = m20 + m02; y = m21 + m12; z = best;     }

    // reference scale = 0.5 / max(sqrt(best), 0.1); best >= 1 always (sum t = 4)
    float scale = 0.5f * rsqrtf(best);

    float nsq = x * x + y * y + z * z;
    float n = nsq * rsqrtf(fmaxf(nsq, 1e-30f));

    // half = atan2(n, w): scale-invariant
    float aw = fabsf(w);
    float mn = fminf(n, aw), mx = fmaxf(n, aw);
    float a = __fdividef(mn, mx);
    float r = fast_atan01(a);
    if (n > aw) r = 1.5707963267948966f - r;
    if (w < 0.0f) r = 3.14159265358979323f - r;

    float angle = 2.0f * r;   // >= 0
    // sin(half) = n/hyp (scale-invariant); inv_s = angle*hyp/n
    // out = (x*scale) * inv_s = x * k  with  k = scale*angle*hyp/n
    float k;
    if (angle < 1e-6f) {
        k = scale * __fdividef(1.0f, 0.5f - angle * angle * (1.0f / 48.0f));
    } else {
        float hsq = fmaf(w, w, nsq);
        float hyp = hsq * rsqrtf(hsq);
        k = scale * __fdividef(angle * hyp, n);
    }
    aa[0] = x * k;
    aa[1] = y * k;
    aa[2] = z * k;
}

__global__ __launch_bounds__(256)
void pose_kernel(const float* __restrict__ glb, const float* __restrict__ ori,
                 float* __restrict__ outp, int n) {
    // per-warp output staging: 2 samples * 72 floats = 144 floats per warp
    __shared__ float stage[8][144];

    int tid = blockIdx.x * blockDim.x + threadIdx.x;
    int lane32 = threadIdx.x & 31;
    int warp_in_block = threadIdx.x >> 5;
    int lane = lane32 & 15;            // joint slot within sample
    int s = tid >> 4;                  // my sample
    int s0 = s & ~1;                   // warp's first sample (even)
    int half = lane32 >> 4;            // 0 or 1: which sample in warp
    if (s0 >= n) return;

    int ss = min(s, n - 1);            // OOB-safe (lanes stay converged)

    // ---- packed lookup tables (no local memory) ----
    bool is_ori = (0xC831u >> lane) & 1u;                              // lanes {0,4,5,11,14,15}
    int row = (int)((0x5498376543212100ULL >> (lane * 4)) & 15);       // row in source array
    int pl  = (int)((0xDCA9877763210000ULL >> (lane * 4)) & 15);       // parent's lane
    int out_j = lane + (lane >= 8 ? 4 : (lane == 7 ? 2 : 0));          // output joint index

    const float* src = is_ori
        ? (ori + ss * 36 + row * 6)
        : (glb + ss * 60 + row * 6);

    float d6[6];
    {
        float2 a = *reinterpret_cast<const float2*>(src);
        float2 b = *reinterpret_cast<const float2*>(src + 2);
        float2 c = *reinterpret_cast<const float2*>(src + 4);
        d6[0] = a.x; d6[1] = a.y; d6[2] = b.x; d6[3] = b.y; d6[4] = c.x; d6[5] = c.y;
    }

    float X[9];
    rot6d_to_mat(d6, X);

    // broadcast root (lane 0 of each 16-lane group)
    float root[9];
#pragma unroll
    for (int i = 0; i < 9; i++)
        root[i] = __shfl_sync(0xffffffffu, X[i], 0, 16);

    // F = root * X. Lane 0's F is never consumed (its children take local root),
    // so no lane-0 fixup needed here.
    float F[9];
#pragma unroll
    for (int i = 0; i < 3; i++)
#pragma unroll
        for (int j = 0; j < 3; j++)
            F[i * 3 + j] = root[i * 3 + 0] * X[0 * 3 + j]
                         + root[i * 3 + 1] * X[1 * 3 + j]
                         + root[i * 3 + 2] * X[2 * 3 + j];

    // parent's global matrix: lanes 0-3 (parent = joint 0) use local root copy
    float Fp[9];
    bool parent_is_root = (lane < 4);
#pragma unroll
    for (int i = 0; i < 9; i++) {
        float v = __shfl_sync(0xffffffffu, F[i], pl, 16);
        Fp[i] = parent_is_root ? root[i] : v;
    }

    // L = Fp^T * F   (lane 0: L = root, semantically required)
    float L[9];
#pragma unroll
    for (int i = 0; i < 3; i++)
#pragma unroll
        for (int j = 0; j < 3; j++)
            L[i * 3 + j] = Fp[0 * 3 + i] * F[0 * 3 + j]
                         + Fp[1 * 3 + i] * F[1 * 3 + j]
                         + Fp[2 * 3 + i] * F[2 * 3 + j];
    if (lane == 0) {
#pragma unroll
        for (int i = 0; i < 9; i++) L[i] = root[i];
    }

    float aa[3];
    mat_to_aa(L, aa);

    // ---- stage into smem ----
    float* w_smem = stage[warp_in_block] + half * 72;
    {
        float* d = w_smem + out_j * 3;
        d[0] = aa[0]; d[1] = aa[1]; d[2] = aa[2];
    }
    // zero ignored joints {7,8,10,11,20,21,22,23}: lanes 0-7 of each sample
    if (lane < 8) {
        int ign = lane + (lane < 2 ? 7 : (lane < 4 ? 8 : 16));
        float* zp = w_smem + ign * 3;
        zp[0] = 0.0f; zp[1] = 0.0f; zp[2] = 0.0f;
    }
    __syncwarp();

    // ---- coalesced float4 writeback: 36 float4 per warp (2 samples x 288B) ----
    {
        int nf4 = (s0 + 1 < n) ? 36 : 18;   // tail never hit for BT=262144
        const float4* src4 = reinterpret_cast<const float4*>(stage[warp_in_block]);
        float4* dst4 = reinterpret_cast<float4*>(outp + (size_t)s0 * 72);
#pragma unroll
        for (int i = lane32; i < 36; i += 32)
            if (i < nf4) dst4[i] = src4[i];
    }
}

extern "C" void kernel_launch(void* const* d_in, const int* in_sizes, int n_in,
                              void* d_out, int out_size) {
    const float* glb = (const float*)d_in[0];
    const float* ori = (const float*)d_in[1];
    float* outp = (float*)d_out;
    int n = in_sizes[0] / 60;                 // BT samples
    long long total = (long long)n * 16;
    int threads = 256;
    int blocks = (int)((total + threads - 1) / threads);
    pose_kernel<<<blocks, threads>>>(glb, ori, outp, n);
}

// round 7
// speedup vs baseline: 1.0514x; 1.0514x over previous
#include <cuda_runtime.h>
#include <cuda_bf16.h>
#include <math.h>

// HumanPoseModule: fused 6D-rot -> FK -> axis-angle
// d_in[0] = glb_reduced_6d (BT,10,6) f32   rows: joints [1,2,3,6,9,12,13,14,16,17]
// d_in[1] = orientation_6d (BT,6,6)  f32   rows: joints [0,4,5,15,18,19]
// out      = (BT,24,3) f32
//
// 16 lanes per sample, one joint per lane; parent matrices via __shfl_sync(width=16).
// Outputs staged per-warp in smem, then written as coalesced float4.
// (Round-4 register structure: lane-0 F fixup, no root-select on Fp.)

__device__ __forceinline__ void rot6d_to_mat(const float* d6, float* m) {
    float a1x = d6[0], a1y = d6[1], a1z = d6[2];
    float a2x = d6[3], a2y = d6[4], a2z = d6[5];
    float r1 = rsqrtf(a1x * a1x + a1y * a1y + a1z * a1z);
    float b1x = a1x * r1, b1y = a1y * r1, b1z = a1z * r1;
    float d = b1x * a2x + b1y * a2y + b1z * a2z;
    float b2x = a2x - d * b1x, b2y = a2y - d * b1y, b2z = a2z - d * b1z;
    float r2 = rsqrtf(b2x * b2x + b2y * b2y + b2z * b2z);
    b2x *= r2; b2y *= r2; b2z *= r2;
    m[0] = b1x; m[1] = b1y; m[2] = b1z;
    m[3] = b2x; m[4] = b2y; m[5] = b2z;
    m[6] = b1y * b2z - b1z * b2y;
    m[7] = b1z * b2x - b1x * b2z;
    m[8] = b1x * b2y - b1y * b2x;
}

// atan(a) for a in [0,1], minimax poly (abs err ~1e-6 rad)
__device__ __forceinline__ float fast_atan01(float a) {
    float s = a * a;
    float r = -0.0117212f;
    r = fmaf(r, s, 0.05265332f);
    r = fmaf(r, s, -0.11643287f);
    r = fmaf(r, s, 0.19354346f);
    r = fmaf(r, s, -0.33262347f);
    r = fmaf(r, s, 0.99997726f);
    return r * a;
}

// matrix -> quaternion -> axis-angle (reference-faithful pivot selection).
// Quaternion scale folded into one output coefficient (atan2 & sin-ratio are
// invariant under positive scaling of (w,x,y,z)).
__device__ __forceinline__ void mat_to_aa(const float* m, float* __restrict__ aa) {
    float m00 = m[0], m01 = m[1], m02 = m[2];
    float m10 = m[3], m11 = m[4], m12 = m[5];
    float m20 = m[6], m21 = m[7], m22 = m[8];

    float t0 = fmaxf(1.0f + m00 + m11 + m22, 0.0f);
    float t1 = fmaxf(1.0f + m00 - m11 - m22, 0.0f);
    float t2 = fmaxf(1.0f - m00 + m11 - m22, 0.0f);
    float t3 = fmaxf(1.0f - m00 - m11 + m22, 0.0f);

    float best = t0; int idx = 0;
    if (t1 > best) { best = t1; idx = 1; }
    if (t2 > best) { best = t2; idx = 2; }
    if (t3 > best) { best = t3; idx = 3; }

    float w, x, y, z;   // UNscaled quaternion (positive multiple of reference's)
    if (idx == 0)      { w = best;      x = m21 - m12; y = m02 - m20; z = m10 - m01; }
    else if (idx == 1) { w = m21 - m12; x = best;      y = m10 + m01; z = m02 + m20; }
    else if (idx == 2) { w = m02 - m20; x = m10 + m01; y = best;      z = m12 + m21; }
    else               { w = m10 - m01; x = m20 + m02; y = m21 + m12; z = best;     }

    // reference scale = 0.5 / max(sqrt(best), 0.1); best >= 1 always (sum t = 4)
    float scale = 0.5f * rsqrtf(best);

    float nsq = x * x + y * y + z * z;
    float n = nsq * rsqrtf(fmaxf(nsq, 1e-30f));

    // half = atan2(n, w): scale-invariant
    float aw = fabsf(w);
    float mn = fminf(n, aw), mx = fmaxf(n, aw);
    float a = __fdividef(mn, mx);
    float r = fast_atan01(a);
    if (n > aw) r = 1.5707963267948966f - r;
    if (w < 0.0f) r = 3.14159265358979323f - r;

    float angle = 2.0f * r;   // >= 0
    // sin(half) = n/hyp (scale-invariant); out = x * k, k = scale*angle*hyp/n
    float k;
    if (angle < 1e-6f) {
        k = scale * __fdividef(1.0f, 0.5f - angle * angle * (1.0f / 48.0f));
    } else {
        float hsq = fmaf(w, w, nsq);
        float hyp = hsq * rsqrtf(hsq);
        k = scale * __fdividef(angle * hyp, n);
    }
    aa[0] = x * k;
    aa[1] = y * k;
    aa[2] = z * k;
}

__global__ __launch_bounds__(256)
void pose_kernel(const float* __restrict__ glb, const float* __restrict__ ori,
                 float* __restrict__ outp, int n) {
    // per-warp output staging: 2 samples * 72 floats = 144 floats per warp
    __shared__ float stage[8][144];

    int tid = blockIdx.x * blockDim.x + threadIdx.x;
    int lane32 = threadIdx.x & 31;
    int warp_in_block = threadIdx.x >> 5;
    int lane = lane32 & 15;            // joint slot within sample
    int s = tid >> 4;                  // my sample
    int s0 = s & ~1;                   // warp's first sample (even)
    int half = lane32 >> 4;            // 0 or 1: which sample in warp

    bool active = (s < n);
    int ss = active ? s : (n - 1);     // clamp for OOB-safe loads (lanes stay converged)

    // ---- packed lookup tables (no local memory) ----
    bool is_ori = (0xC831u >> lane) & 1u;                              // lanes {0,4,5,11,14,15}
    int row = (int)((0x5498376543212100ULL >> (lane * 4)) & 15);       // row in source array
    int pl  = (int)((0xDCA9877763210000ULL >> (lane * 4)) & 15);       // parent's lane
    int out_j = lane + (lane >= 8 ? 4 : (lane == 7 ? 2 : 0));          // output joint index

    const float* src = is_ori
        ? (ori + (size_t)ss * 36 + row * 6)
        : (glb + (size_t)ss * 60 + row * 6);

    float d6[6];
    {
        float2 a = *reinterpret_cast<const float2*>(src);
        float2 b = *reinterpret_cast<const float2*>(src + 2);
        float2 c = *reinterpret_cast<const float2*>(src + 4);
        d6[0] = a.x; d6[1] = a.y; d6[2] = b.x; d6[3] = b.y; d6[4] = c.x; d6[5] = c.y;
    }

    float X[9];
    rot6d_to_mat(d6, X);

    // broadcast root (lane 0 of each 16-lane group)
    float root[9];
#pragma unroll
    for (int i = 0; i < 9; i++)
        root[i] = __shfl_sync(0xffffffffu, X[i], 0, 16);

    // F = root * X  (lane 0: F = root itself, fixup below)
    float F[9];
#pragma unroll
    for (int i = 0; i < 3; i++)
#pragma unroll
        for (int j = 0; j < 3; j++)
            F[i * 3 + j] = root[i * 3 + 0] * X[0 * 3 + j]
                         + root[i * 3 + 1] * X[1 * 3 + j]
                         + root[i * 3 + 2] * X[2 * 3 + j];
    if (lane == 0) {
#pragma unroll
        for (int i = 0; i < 9; i++) F[i] = X[i];
    }

    // fetch parent's F (lane 0 holds root after fixup; lanes 1-3 have pl=0)
    float Fp[9];
#pragma unroll
    for (int i = 0; i < 9; i++)
        Fp[i] = __shfl_sync(0xffffffffu, F[i], pl, 16);

    // L = Fp^T * F   (lane 0: L = root, semantically required)
    float L[9];
#pragma unroll
    for (int i = 0; i < 3; i++)
#pragma unroll
        for (int j = 0; j < 3; j++)
            L[i * 3 + j] = Fp[0 * 3 + i] * F[0 * 3 + j]
                         + Fp[1 * 3 + i] * F[1 * 3 + j]
                         + Fp[2 * 3 + i] * F[2 * 3 + j];
    if (lane == 0) {
#pragma unroll
        for (int i = 0; i < 9; i++) L[i] = F[i];
    }

    float aa[3];
    mat_to_aa(L, aa);

    // ---- stage into smem ----
    float* w_smem = stage[warp_in_block] + half * 72;
    {
        float* d = w_smem + out_j * 3;
        d[0] = aa[0]; d[1] = aa[1]; d[2] = aa[2];
    }
    // zero ignored joints {7,8,10,11,20,21,22,23}: lanes 0-7 of each sample
    if (lane < 8) {
        int ign = lane + (lane < 2 ? 7 : (lane < 4 ? 8 : 16));
        float* zp = w_smem + ign * 3;
        zp[0] = 0.0f; zp[1] = 0.0f; zp[2] = 0.0f;
    }
    __syncwarp();

    // ---- coalesced float4 writeback: 36 float4 per warp (2 samples x 288B) ----
    {
        int rem = n - s0;
        int nf4 = (rem >= 2) ? 36 : (rem == 1 ? 18 : 0);
        const float4* src4 = reinterpret_cast<const float4*>(stage[warp_in_block]);
        float4* dst4 = reinterpret_cast<float4*>(outp + (size_t)s0 * 72);
#pragma unroll
        for (int i = lane32; i < 36; i += 32)
            if (i < nf4) dst4[i] = src4[i];
    }
}

extern "C" void kernel_launch(void* const* d_in, const int* in_sizes, int n_in,
                              void* d_out, int out_size) {
    const float* glb = (const float*)d_in[0];
    const float* ori = (const float*)d_in[1];
    float* outp = (float*)d_out;
    int n = in_sizes[0] / 60;                 // BT samples
    long long total = (long long)n * 16;
    int threads = 256;
    int blocks = (int)((total + threads - 1) / threads);
    pose_kernel<<<blocks, threads>>>(glb, ori, outp, n);
}

// round 8
// speedup vs baseline: 1.1813x; 1.1235x over previous
#include <cuda_runtime.h>
#include <cuda_bf16.h>
#include <math.h>

// HumanPoseModule: fused 6D-rot -> FK -> axis-angle
// d_in[0] = glb_reduced_6d (BT,10,6) f32   rows: joints [1,2,3,6,9,12,13,14,16,17]
// d_in[1] = orientation_6d (BT,6,6)  f32   rows: joints [0,4,5,15,18,19]
// out      = (BT,24,3) f32
//
// 16 lanes per sample, one joint per lane.
// Algebraic simplification: L_j = F_p^T F_j = X_p^T (root^T root) X_j ~= X_p^T X_j
// (root is Gram-Schmidt orthonormal, root^T root = I to fp rounding), so the
// root broadcast and the root*X premultiply are eliminated entirely.
// Lanes 0-3 use X_p = I (exact identity via immediates): lane0 -> L = root,
// lanes 1-3 -> L = X.

__device__ __forceinline__ void rot6d_to_mat(const float* d6, float* m) {
    float a1x = d6[0], a1y = d6[1], a1z = d6[2];
    float a2x = d6[3], a2y = d6[4], a2z = d6[5];
    float r1 = rsqrtf(a1x * a1x + a1y * a1y + a1z * a1z);
    float b1x = a1x * r1, b1y = a1y * r1, b1z = a1z * r1;
    float d = b1x * a2x + b1y * a2y + b1z * a2z;
    float b2x = a2x - d * b1x, b2y = a2y - d * b1y, b2z = a2z - d * b1z;
    float r2 = rsqrtf(b2x * b2x + b2y * b2y + b2z * b2z);
    b2x *= r2; b2y *= r2; b2z *= r2;
    m[0] = b1x; m[1] = b1y; m[2] = b1z;
    m[3] = b2x; m[4] = b2y; m[5] = b2z;
    m[6] = b1y * b2z - b1z * b2y;
    m[7] = b1z * b2x - b1x * b2z;
    m[8] = b1x * b2y - b1y * b2x;
}

// atan(a) for a in [0,1], minimax poly (abs err ~1e-6 rad)
__device__ __forceinline__ float fast_atan01(float a) {
    float s = a * a;
    float r = -0.0117212f;
    r = fmaf(r, s, 0.05265332f);
    r = fmaf(r, s, -0.11643287f);
    r = fmaf(r, s, 0.19354346f);
    r = fmaf(r, s, -0.33262347f);
    r = fmaf(r, s, 0.99997726f);
    return r * a;
}

// matrix -> quaternion -> axis-angle (reference-faithful pivot selection).
// Quaternion scale folded into one output coefficient (atan2 & sin-ratio are
// invariant under positive scaling of (w,x,y,z)).
__device__ __forceinline__ void mat_to_aa(const float* m, float* __restrict__ aa) {
    float m00 = m[0], m01 = m[1], m02 = m[2];
    float m10 = m[3], m11 = m[4], m12 = m[5];
    float m20 = m[6], m21 = m[7], m22 = m[8];

    float t0 = fmaxf(1.0f + m00 + m11 + m22, 0.0f);
    float t1 = fmaxf(1.0f + m00 - m11 - m22, 0.0f);
    float t2 = fmaxf(1.0f - m00 + m11 - m22, 0.0f);
    float t3 = fmaxf(1.0f - m00 - m11 + m22, 0.0f);

    float best = t0; int idx = 0;
    if (t1 > best) { best = t1; idx = 1; }
    if (t2 > best) { best = t2; idx = 2; }
    if (t3 > best) { best = t3; idx = 3; }

    float w, x, y, z;   // UNscaled quaternion (positive multiple of reference's)
    if (idx == 0)      { w = best;      x = m21 - m12; y = m02 - m20; z = m10 - m01; }
    else if (idx == 1) { w = m21 - m12; x = best;      y = m10 + m01; z = m02 + m20; }
    else if (idx == 2) { w = m02 - m20; x = m10 + m01; y = best;      z = m12 + m21; }
    else               { w = m10 - m01; x = m20 + m02; y = m21 + m12; z = best;     }

    // reference scale = 0.5 / max(sqrt(best), 0.1); best >= 1 always (sum t = 4)
    float scale = 0.5f * rsqrtf(best);

    float nsq = x * x + y * y + z * z;
    float n = nsq * rsqrtf(fmaxf(nsq, 1e-30f));

    // half = atan2(n, w): scale-invariant
    float aw = fabsf(w);
    float mn = fminf(n, aw), mx = fmaxf(n, aw);
    float a = __fdividef(mn, mx);
    float r = fast_atan01(a);
    if (n > aw) r = 1.5707963267948966f - r;
    if (w < 0.0f) r = 3.14159265358979323f - r;

    float angle = 2.0f * r;   // >= 0
    // sin(half) = n/hyp (scale-invariant); out = x * k, k = scale*angle*hyp/n
    float k;
    if (angle < 1e-6f) {
        k = scale * __fdividef(1.0f, 0.5f - angle * angle * (1.0f / 48.0f));
    } else {
        float hsq = fmaf(w, w, nsq);
        float hyp = hsq * rsqrtf(hsq);
        k = scale * __fdividef(angle * hyp, n);
    }
    aa[0] = x * k;
    aa[1] = y * k;
    aa[2] = z * k;
}

__global__ __launch_bounds__(256)
void pose_kernel(const float* __restrict__ glb, const float* __restrict__ ori,
                 float* __restrict__ outp, int n) {
    // per-warp output staging: 2 samples * 72 floats = 144 floats per warp
    __shared__ float stage[8][144];

    int tid = blockIdx.x * blockDim.x + threadIdx.x;
    int lane32 = threadIdx.x & 31;
    int warp_in_block = threadIdx.x >> 5;
    int lane = lane32 & 15;            // joint slot within sample
    int s = tid >> 4;                  // my sample
    int s0 = s & ~1;                   // warp's first sample (even)
    int half = lane32 >> 4;            // 0 or 1: which sample in warp

    bool active = (s < n);
    int ss = active ? s : (n - 1);     // clamp for OOB-safe loads (lanes stay converged)

    // ---- packed lookup tables (no local memory) ----
    bool is_ori = (0xC831u >> lane) & 1u;                              // lanes {0,4,5,11,14,15}
    int row = (int)((0x5498376543212100ULL >> (lane * 4)) & 15);       // row in source array
    int pl  = (int)((0xDCA9877763210000ULL >> (lane * 4)) & 15);       // parent's lane
    int out_j = lane + (lane >= 8 ? 4 : (lane == 7 ? 2 : 0));          // output joint index

    const float* src = is_ori
        ? (ori + (size_t)ss * 36 + row * 6)
        : (glb + (size_t)ss * 60 + row * 6);

    float d6[6];
    {
        float2 a = *reinterpret_cast<const float2*>(src);
        float2 b = *reinterpret_cast<const float2*>(src + 2);
        float2 c = *reinterpret_cast<const float2*>(src + 4);
        d6[0] = a.x; d6[1] = a.y; d6[2] = b.x; d6[3] = b.y; d6[4] = c.x; d6[5] = c.y;
    }

    float X[9];
    rot6d_to_mat(d6, X);

    // parent's rotation: shuffle X from parent's lane; lanes 0-3 substitute
    // exact identity (immediates -> no extra register pressure).
    // I^T * X = X exactly in fp (1*x + 0*y + 0*z via fma chain).
    bool root_parent = (lane < 4);
    float Xp[9];
#pragma unroll
    for (int i = 0; i < 9; i++) {
        float v = __shfl_sync(0xffffffffu, X[i], pl, 16);
        float id = (i == 0 || i == 4 || i == 8) ? 1.0f : 0.0f;
        Xp[i] = root_parent ? id : v;
    }

    // L = Xp^T * X
    float L[9];
#pragma unroll
    for (int i = 0; i < 3; i++)
#pragma unroll
        for (int j = 0; j < 3; j++)
            L[i * 3 + j] = Xp[0 * 3 + i] * X[0 * 3 + j]
                         + Xp[1 * 3 + i] * X[1 * 3 + j]
                         + Xp[2 * 3 + i] * X[2 * 3 + j];

    float aa[3];
    mat_to_aa(L, aa);

    // ---- stage into smem ----
    float* w_smem = stage[warp_in_block] + half * 72;
    {
        float* d = w_smem + out_j * 3;
        d[0] = aa[0]; d[1] = aa[1]; d[2] = aa[2];
    }
    // zero ignored joints {7,8,10,11,20,21,22,23}: lanes 0-7 of each sample
    if (lane < 8) {
        int ign = lane + (lane < 2 ? 7 : (lane < 4 ? 8 : 16));
        float* zp = w_smem + ign * 3;
        zp[0] = 0.0f; zp[1] = 0.0f; zp[2] = 0.0f;
    }
    __syncwarp();

    // ---- coalesced float4 writeback: 36 float4 per warp (2 samples x 288B) ----
    {
        int rem = n - s0;
        int nf4 = (rem >= 2) ? 36 : (rem == 1 ? 18 : 0);
        const float4* src4 = reinterpret_cast<const float4*>(stage[warp_in_block]);
        float4* dst4 = reinterpret_cast<float4*>(outp + (size_t)s0 * 72);
#pragma unroll
        for (int i = lane32; i < 36; i += 32)
            if (i < nf4) dst4[i] = src4[i];
    }
}

extern "C" void kernel_launch(void* const* d_in, const int* in_sizes, int n_in,
                              void* d_out, int out_size) {
    const float* glb = (const float*)d_in[0];
    const float* ori = (const float*)d_in[1];
    float* outp = (float*)d_out;
    int n = in_sizes[0] / 60;                 // BT samples
    long long total = (long long)n * 16;
    int threads = 256;
    int blocks = (int)((total + threads - 1) / threads);
    pose_kernel<<<blocks, threads>>>(glb, ori, outp, n);
}

// round 9
// speedup vs baseline: 1.2479x; 1.0564x over previous
#include <cuda_runtime.h>
#include <cuda_bf16.h>
#include <math.h>

// HumanPoseModule: fused 6D-rot -> FK -> axis-angle
// d_in[0] = glb_reduced_6d (BT,10,6) f32   rows: joints [1,2,3,6,9,12,13,14,16,17]
// d_in[1] = orientation_6d (BT,6,6)  f32   rows: joints [0,4,5,15,18,19]
// out      = (BT,24,3) f32
//
// Packed f32x2: each lane handles its joint for TWO samples (lo/hi of a 64-bit
// register pair); warp covers 4 samples. rot6d + the 3x3 matmul run packed
// (fma.rn.f32x2 -> FFMA2, one issue slot per two fp32 ops); mat_to_aa stays
// scalar per half (branchy argmax/select logic). L = Xp^T X with root^T root = I
// elimination as in round 8.

typedef unsigned long long u64;

__device__ __forceinline__ u64 f2pack(float lo, float hi) {
    u64 r; asm("mov.b64 %0, {%1, %2};" : "=l"(r) : "f"(lo), "f"(hi)); return r;
}
__device__ __forceinline__ float f2lo(u64 v) {
    float lo, hi; asm("mov.b64 {%0, %1}, %2;" : "=f"(lo), "=f"(hi) : "l"(v)); return lo;
}
__device__ __forceinline__ float f2hi(u64 v) {
    float lo, hi; asm("mov.b64 {%0, %1}, %2;" : "=f"(lo), "=f"(hi) : "l"(v)); return hi;
}
__device__ __forceinline__ u64 f2mul(u64 a, u64 b) {
    u64 r; asm("mul.rn.f32x2 %0, %1, %2;" : "=l"(r) : "l"(a), "l"(b)); return r;
}
__device__ __forceinline__ u64 f2fma(u64 a, u64 b, u64 c) {
    u64 r; asm("fma.rn.f32x2 %0, %1, %2, %3;" : "=l"(r) : "l"(a), "l"(b), "l"(c)); return r;
}
__device__ __forceinline__ u64 f2rsqrt(u64 a) {
    return f2pack(rsqrtf(f2lo(a)), rsqrtf(f2hi(a)));
}

static __device__ const u64 F2_NEG1 = 0xBF800000BF800000ULL;  // (-1.0f, -1.0f)

// packed Gram-Schmidt 6d -> rotation matrix (rows)
__device__ __forceinline__ void rot6d_f2(const u64* d6, u64* m) {
    u64 a1x = d6[0], a1y = d6[1], a1z = d6[2];
    u64 a2x = d6[3], a2y = d6[4], a2z = d6[5];
    u64 n1 = f2fma(a1x, a1x, f2fma(a1y, a1y, f2mul(a1z, a1z)));
    u64 r1 = f2rsqrt(n1);
    u64 b1x = f2mul(a1x, r1), b1y = f2mul(a1y, r1), b1z = f2mul(a1z, r1);
    u64 d = f2fma(b1x, a2x, f2fma(b1y, a2y, f2mul(b1z, a2z)));
    u64 dn = f2mul(d, F2_NEG1);
    u64 b2x = f2fma(dn, b1x, a2x);
    u64 b2y = f2fma(dn, b1y, a2y);
    u64 b2z = f2fma(dn, b1z, a2z);
    u64 n2 = f2fma(b2x, b2x, f2fma(b2y, b2y, f2mul(b2z, b2z)));
    u64 r2 = f2rsqrt(n2);
    b2x = f2mul(b2x, r2); b2y = f2mul(b2y, r2); b2z = f2mul(b2z, r2);
    m[0] = b1x; m[1] = b1y; m[2] = b1z;
    m[3] = b2x; m[4] = b2y; m[5] = b2z;
    m[6] = f2fma(b1y, b2z, f2mul(f2mul(b1z, b2y), F2_NEG1));
    m[7] = f2fma(b1z, b2x, f2mul(f2mul(b1x, b2z), F2_NEG1));
    m[8] = f2fma(b1x, b2y, f2mul(f2mul(b1y, b2x), F2_NEG1));
}

// atan(a) for a in [0,1], minimax poly (abs err ~1e-6 rad)
__device__ __forceinline__ float fast_atan01(float a) {
    float s = a * a;
    float r = -0.0117212f;
    r = fmaf(r, s, 0.05265332f);
    r = fmaf(r, s, -0.11643287f);
    r = fmaf(r, s, 0.19354346f);
    r = fmaf(r, s, -0.33262347f);
    r = fmaf(r, s, 0.99997726f);
    return r * a;
}

// matrix -> quaternion -> axis-angle (reference-faithful pivot selection).
// Clamps on t dropped (argmax unaffected: max >= 1 since sum t = 4; clamping
// only lifts negatives to 0, which can never reach or tie the max).
__device__ __forceinline__ void mat_to_aa(const float* m, float* __restrict__ aa) {
    float m00 = m[0], m01 = m[1], m02 = m[2];
    float m10 = m[3], m11 = m[4], m12 = m[5];
    float m20 = m[6], m21 = m[7], m22 = m[8];

    float t0 = 1.0f + m00 + m11 + m22;
    float t1 = 1.0f + m00 - m11 - m22;
    float t2 = 1.0f - m00 + m11 - m22;
    float t3 = 1.0f - m00 - m11 + m22;

    float best = t0; int idx = 0;
    if (t1 > best) { best = t1; idx = 1; }
    if (t2 > best) { best = t2; idx = 2; }
    if (t3 > best) { best = t3; idx = 3; }

    float w, x, y, z;   // UNscaled quaternion (positive multiple of reference's)
    if (idx == 0)      { w = best;      x = m21 - m12; y = m02 - m20; z = m10 - m01; }
    else if (idx == 1) { w = m21 - m12; x = best;      y = m10 + m01; z = m02 + m20; }
    else if (idx == 2) { w = m02 - m20; x = m10 + m01; y = best;      z = m12 + m21; }
    else               { w = m10 - m01; x = m20 + m02; y = m21 + m12; z = best;     }

    // reference scale = 0.5 / max(sqrt(best), 0.1); best >= 1 always
    float scale = 0.5f * rsqrtf(best);

    float nsq = x * x + y * y + z * z;
    float rn = rsqrtf(fmaxf(nsq, 1e-30f));   // rn = 1/n
    float n = nsq * rn;

    // half = atan2(n, w): scale-invariant
    float aw = fabsf(w);
    float mn = fminf(n, aw), mx = fmaxf(n, aw);
    float a = __fdividef(mn, mx);
    float r = fast_atan01(a);
    if (n > aw) r = 1.5707963267948966f - r;
    if (w < 0.0f) r = 3.14159265358979323f - r;

    float angle = 2.0f * r;   // >= 0
    // sin(half) = n/hyp; out = x*k, k = scale*angle*hyp/n = scale*angle*hyp*rn
    float k;
    if (angle < 1e-6f) {
        k = scale * __fdividef(1.0f, 0.5f - angle * angle * (1.0f / 48.0f));
    } else {
        float hsq = fmaf(w, w, nsq);
        float hyp = hsq * rsqrtf(hsq);
        k = scale * (angle * hyp * rn);
    }
    aa[0] = x * k;
    aa[1] = y * k;
    aa[2] = z * k;
}

__global__ __launch_bounds__(256)
void pose_kernel(const float* __restrict__ glb, const float* __restrict__ ori,
                 float* __restrict__ outp, int n) {
    // per-warp staging: 4 samples * 72 floats
    __shared__ float stage[8][288];

    int l = threadIdx.x & 31;
    int warp_in_block = threadIdx.x >> 5;
    int w = (blockIdx.x * blockDim.x + threadIdx.x) >> 5;   // global warp id
    int slot = l & 15;       // joint slot
    int pair = l >> 4;       // which sample-pair in the warp

    if (w * 4 >= n) return;
    int p0 = w * 4 + pair * 2;
    int pa = min(p0, n - 1);
    int pb = min(p0 + 1, n - 1);

    // ---- packed lookup tables (no local memory) ----
    bool is_ori = (0xC831u >> slot) & 1u;                              // slots {0,4,5,11,14,15}
    int row = (int)((0x5498376543212100ULL >> (slot * 4)) & 15);       // row in source array
    int pl  = (int)((0xDCA9877763210000ULL >> (slot * 4)) & 15);       // parent's slot
    int out_j = slot + (slot >= 8 ? 4 : (slot == 7 ? 2 : 0));          // output joint index

    const float* Sa = is_ori ? (ori + (size_t)pa * 36 + row * 6)
                             : (glb + (size_t)pa * 60 + row * 6);
    const float* Sb = is_ori ? (ori + (size_t)pb * 36 + row * 6)
                             : (glb + (size_t)pb * 60 + row * 6);

    u64 d6[6];
    {
        float2 a0 = *reinterpret_cast<const float2*>(Sa);
        float2 a1 = *reinterpret_cast<const float2*>(Sa + 2);
        float2 a2 = *reinterpret_cast<const float2*>(Sa + 4);
        float2 b0 = *reinterpret_cast<const float2*>(Sb);
        float2 b1 = *reinterpret_cast<const float2*>(Sb + 2);
        float2 b2 = *reinterpret_cast<const float2*>(Sb + 4);
        d6[0] = f2pack(a0.x, b0.x); d6[1] = f2pack(a0.y, b0.y);
        d6[2] = f2pack(a1.x, b1.x); d6[3] = f2pack(a1.y, b1.y);
        d6[4] = f2pack(a2.x, b2.x); d6[5] = f2pack(a2.y, b2.y);
    }

    u64 X[9];
    rot6d_f2(d6, X);

    // parent's rotation (packed): width-16 shuffle within each half-warp
    u64 Xp[9];
#pragma unroll
    for (int i = 0; i < 9; i++)
        Xp[i] = __shfl_sync(0xffffffffu, X[i], pl, 16);

    // L = Xp^T * X (packed); slots 0-3 (parent = root) take L = X exactly:
    // slot 0 -> L = root (= its own X), slots 1-3 -> L = X (root^T root = I).
    bool root_parent = (slot < 4);
    u64 L[9];
#pragma unroll
    for (int i = 0; i < 3; i++)
#pragma unroll
        for (int j = 0; j < 3; j++) {
            u64 v = f2fma(Xp[0 * 3 + i], X[0 * 3 + j],
                    f2fma(Xp[1 * 3 + i], X[1 * 3 + j],
                    f2mul(Xp[2 * 3 + i], X[2 * 3 + j])));
            L[i * 3 + j] = root_parent ? X[i * 3 + j] : v;
        }

    // unpack halves and finish scalar
    float La[9], Lb[9];
#pragma unroll
    for (int i = 0; i < 9; i++) { La[i] = f2lo(L[i]); Lb[i] = f2hi(L[i]); }

    float aaA[3], aaB[3];
    mat_to_aa(La, aaA);
    mat_to_aa(Lb, aaB);

    // ---- stage into smem ----
    float* ws = stage[warp_in_block];
    int qA = pair * 2, qB = qA + 1;
    {
        float* dA = ws + qA * 72 + out_j * 3;
        dA[0] = aaA[0]; dA[1] = aaA[1]; dA[2] = aaA[2];
        float* dB = ws + qB * 72 + out_j * 3;
        dB[0] = aaB[0]; dB[1] = aaB[1]; dB[2] = aaB[2];
    }
    // zero ignored joints {7,8,10,11,20,21,22,23} for both samples
    if (slot < 8) {
        int ign = slot + (slot < 2 ? 7 : (slot < 4 ? 8 : 16));
        float* zA = ws + qA * 72 + ign * 3;
        zA[0] = 0.0f; zA[1] = 0.0f; zA[2] = 0.0f;
        float* zB = ws + qB * 72 + ign * 3;
        zB[0] = 0.0f; zB[1] = 0.0f; zB[2] = 0.0f;
    }
    __syncwarp();

    // ---- coalesced float4 writeback: up to 72 float4 per warp (4 samples) ----
    {
        int rem = min(n - w * 4, 4);
        int nf4 = rem * 18;
        const float4* s4 = reinterpret_cast<const float4*>(ws);
        float4* dst4 = reinterpret_cast<float4*>(outp + (size_t)w * 288);
        for (int i = l; i < nf4; i += 32)
            dst4[i] = s4[i];
    }
}

extern "C" void kernel_launch(void* const* d_in, const int* in_sizes, int n_in,
                              void* d_out, int out_size) {
    const float* glb = (const float*)d_in[0];
    const float* ori = (const float*)d_in[1];
    float* outp = (float*)d_out;
    int n = in_sizes[0] / 60;                       // BT samples
    long long warps = ((long long)n + 3) / 4;       // 4 samples per warp
    int blocks = (int)((warps + 7) / 8);            // 8 warps per block
    pose_kernel<<<blocks, 256>>>(glb, ori, outp, n);
}